// round 1
// baseline (speedup 1.0000x reference)
#include <cuda_runtime.h>
#include <stdint.h>

#define NBINS   100
#define NCOPIES 8
#define THREADS 256
#define GRID    1184   // 148 SMs * 8 blocks

__device__ unsigned int g_min_ord;
__device__ unsigned int g_max_ord;
__device__ unsigned int g_hist[NBINS];

// Order-preserving float <-> uint mapping (handles negatives correctly)
__device__ __forceinline__ unsigned int f2ord(float f) {
    unsigned int u = __float_as_uint(f);
    return (u & 0x80000000u) ? ~u : (u | 0x80000000u);
}
__device__ __forceinline__ float ord2f(unsigned int o) {
    unsigned int u = (o & 0x80000000u) ? (o ^ 0x80000000u) : ~o;
    return __uint_as_float(u);
}

__global__ void init_kernel() {
    int t = threadIdx.x;
    if (t == 0) {
        g_min_ord = 0xFFFFFFFFu;
        g_max_ord = 0u;
    }
    for (int i = t; i < NBINS; i += blockDim.x) g_hist[i] = 0u;
}

__global__ void __launch_bounds__(THREADS) minmax_kernel(const float* __restrict__ x, int n) {
    int n4 = n >> 2;
    const float4* __restrict__ x4 = (const float4*)x;

    float mn =  3.402823466e+38f;
    float mx = -3.402823466e+38f;

    int stride = gridDim.x * blockDim.x;
    for (int i = blockIdx.x * blockDim.x + threadIdx.x; i < n4; i += stride) {
        float4 v = x4[i];
        mn = fminf(mn, fminf(fminf(v.x, v.y), fminf(v.z, v.w)));
        mx = fmaxf(mx, fmaxf(fmaxf(v.x, v.y), fmaxf(v.z, v.w)));
    }
    // scalar tail (n % 4), handled by block 0
    if (blockIdx.x == 0) {
        int base = n4 << 2;
        for (int i = base + threadIdx.x; i < n; i += blockDim.x) {
            float v = x[i];
            mn = fminf(mn, v);
            mx = fmaxf(mx, v);
        }
    }

    // warp reduce
    #pragma unroll
    for (int o = 16; o > 0; o >>= 1) {
        mn = fminf(mn, __shfl_xor_sync(0xFFFFFFFFu, mn, o));
        mx = fmaxf(mx, __shfl_xor_sync(0xFFFFFFFFu, mx, o));
    }
    // block reduce
    __shared__ float smn[THREADS / 32];
    __shared__ float smx[THREADS / 32];
    int wid = threadIdx.x >> 5;
    int lid = threadIdx.x & 31;
    if (lid == 0) { smn[wid] = mn; smx[wid] = mx; }
    __syncthreads();
    if (wid == 0) {
        mn = (lid < THREADS / 32) ? smn[lid] :  3.402823466e+38f;
        mx = (lid < THREADS / 32) ? smx[lid] : -3.402823466e+38f;
        #pragma unroll
        for (int o = 4; o > 0; o >>= 1) {
            mn = fminf(mn, __shfl_xor_sync(0xFFFFFFFFu, mn, o));
            mx = fmaxf(mx, __shfl_xor_sync(0xFFFFFFFFu, mx, o));
        }
        if (lid == 0) {
            atomicMin(&g_min_ord, f2ord(mn));
            atomicMax(&g_max_ord, f2ord(mx));
        }
    }
}

__device__ __forceinline__ int bin_of(float x, float hmin, float scale) {
    int b = (int)floorf((x - hmin) * scale);
    return min(max(b, 0), NBINS - 1);
}

__global__ void __launch_bounds__(THREADS) hist_kernel(const float* __restrict__ x, int n) {
    __shared__ unsigned int sh[NCOPIES * NBINS];
    for (int i = threadIdx.x; i < NCOPIES * NBINS; i += blockDim.x) sh[i] = 0u;
    __syncthreads();

    float hmin = ord2f(g_min_ord);
    float hmax = ord2f(g_max_ord);
    if (hmax == hmin) hmax = hmin + 1.0f;  // degenerate-range guard (matches reference)
    float scale = (float)NBINS / (hmax - hmin);

    unsigned int* my = sh + ((threadIdx.x >> 5) & (NCOPIES - 1)) * NBINS;

    int n4 = n >> 2;
    const float4* __restrict__ x4 = (const float4*)x;
    int stride = gridDim.x * blockDim.x;
    for (int i = blockIdx.x * blockDim.x + threadIdx.x; i < n4; i += stride) {
        float4 v = x4[i];
        atomicAdd(&my[bin_of(v.x, hmin, scale)], 1u);
        atomicAdd(&my[bin_of(v.y, hmin, scale)], 1u);
        atomicAdd(&my[bin_of(v.z, hmin, scale)], 1u);
        atomicAdd(&my[bin_of(v.w, hmin, scale)], 1u);
    }
    if (blockIdx.x == 0) {
        int base = n4 << 2;
        for (int i = base + threadIdx.x; i < n; i += blockDim.x) {
            atomicAdd(&my[bin_of(x[i], hmin, scale)], 1u);
        }
    }
    __syncthreads();

    // reduce replicas, one global atomic per (block, bin)
    for (int b = threadIdx.x; b < NBINS; b += blockDim.x) {
        unsigned int s = 0;
        #pragma unroll
        for (int c = 0; c < NCOPIES; c++) s += sh[c * NBINS + b];
        if (s) atomicAdd(&g_hist[b], s);
    }
}

__global__ void finalize_kernel(float* __restrict__ out) {
    int i = threadIdx.x;
    if (i < NBINS) out[i] = (float)g_hist[i];
}

extern "C" void kernel_launch(void* const* d_in, const int* in_sizes, int n_in,
                              void* d_out, int out_size) {
    const float* x = (const float*)d_in[0];
    int n = in_sizes[0];
    float* out = (float*)d_out;

    init_kernel<<<1, 128>>>();
    minmax_kernel<<<GRID, THREADS>>>(x, n);
    hist_kernel<<<GRID, THREADS>>>(x, n);
    finalize_kernel<<<1, 128>>>(out);
}

// round 2
// speedup vs baseline: 1.0204x; 1.0204x over previous
#include <cuda_runtime.h>
#include <stdint.h>

#define NBINS   100
#define NCOPIES 8
#define THREADS 256
#define GRID    1184   // 148 SMs * 8 blocks of 256 thr

__device__ float        g_bmin[GRID];
__device__ float        g_bmax[GRID];
__device__ unsigned int g_hist[NBINS];   // zero-init at load; last block restores zero
__device__ unsigned int g_done;          // ticket counter; restored to 0 each run

__global__ void __launch_bounds__(THREADS) minmax_kernel(const float* __restrict__ x, int n) {
    int n4 = n >> 2;
    const float4* __restrict__ x4 = (const float4*)x;

    float mn =  3.402823466e+38f;
    float mx = -3.402823466e+38f;

    const int stride = GRID * THREADS;
    int i = blockIdx.x * THREADS + threadIdx.x;

    // unrolled x4 — 4 independent LDG.128 in flight per warp
    for (; i + 3 * stride < n4; i += 4 * stride) {
        float4 v0 = x4[i];
        float4 v1 = x4[i + stride];
        float4 v2 = x4[i + 2 * stride];
        float4 v3 = x4[i + 3 * stride];
        mn = fminf(mn, fminf(fminf(v0.x, v0.y), fminf(v0.z, v0.w)));
        mx = fmaxf(mx, fmaxf(fmaxf(v0.x, v0.y), fmaxf(v0.z, v0.w)));
        mn = fminf(mn, fminf(fminf(v1.x, v1.y), fminf(v1.z, v1.w)));
        mx = fmaxf(mx, fmaxf(fmaxf(v1.x, v1.y), fmaxf(v1.z, v1.w)));
        mn = fminf(mn, fminf(fminf(v2.x, v2.y), fminf(v2.z, v2.w)));
        mx = fmaxf(mx, fmaxf(fmaxf(v2.x, v2.y), fmaxf(v2.z, v2.w)));
        mn = fminf(mn, fminf(fminf(v3.x, v3.y), fminf(v3.z, v3.w)));
        mx = fmaxf(mx, fmaxf(fmaxf(v3.x, v3.y), fmaxf(v3.z, v3.w)));
    }
    for (; i < n4; i += stride) {
        float4 v = x4[i];
        mn = fminf(mn, fminf(fminf(v.x, v.y), fminf(v.z, v.w)));
        mx = fmaxf(mx, fmaxf(fmaxf(v.x, v.y), fmaxf(v.z, v.w)));
    }
    // scalar tail (n % 4): block 0
    if (blockIdx.x == 0) {
        int base = n4 << 2;
        for (int j = base + threadIdx.x; j < n; j += THREADS) {
            float v = x[j];
            mn = fminf(mn, v);
            mx = fmaxf(mx, v);
        }
    }

    // warp reduce
    #pragma unroll
    for (int o = 16; o > 0; o >>= 1) {
        mn = fminf(mn, __shfl_xor_sync(0xFFFFFFFFu, mn, o));
        mx = fmaxf(mx, __shfl_xor_sync(0xFFFFFFFFu, mx, o));
    }
    __shared__ float smn[THREADS / 32];
    __shared__ float smx[THREADS / 32];
    int wid = threadIdx.x >> 5;
    int lid = threadIdx.x & 31;
    if (lid == 0) { smn[wid] = mn; smx[wid] = mx; }
    __syncthreads();
    if (wid == 0) {
        mn = (lid < THREADS / 32) ? smn[lid] :  3.402823466e+38f;
        mx = (lid < THREADS / 32) ? smx[lid] : -3.402823466e+38f;
        #pragma unroll
        for (int o = 4; o > 0; o >>= 1) {
            mn = fminf(mn, __shfl_xor_sync(0xFFFFFFFFu, mn, o));
            mx = fmaxf(mx, __shfl_xor_sync(0xFFFFFFFFu, mx, o));
        }
        if (lid == 0) {
            g_bmin[blockIdx.x] = mn;   // plain store — no init, no atomic
            g_bmax[blockIdx.x] = mx;
        }
    }
}

__device__ __forceinline__ int bin_of(float x, float hmin, float scale) {
    int b = __float2int_rd((x - hmin) * scale);   // floor + cvt fused
    return min(max(b, 0), NBINS - 1);
}

__global__ void __launch_bounds__(THREADS) hist_kernel(const float* __restrict__ x, int n,
                                                       float* __restrict__ out) {
    __shared__ unsigned int sh[NCOPIES * NBINS];
    __shared__ float s_hmin, s_hmax;

    // ---- re-reduce per-block min/max from L2 (overlaps with smem zeroing) ----
    {
        float mn =  3.402823466e+38f;
        float mx = -3.402823466e+38f;
        for (int j = threadIdx.x; j < GRID; j += THREADS) {
            mn = fminf(mn, g_bmin[j]);
            mx = fmaxf(mx, g_bmax[j]);
        }
        #pragma unroll
        for (int o = 16; o > 0; o >>= 1) {
            mn = fminf(mn, __shfl_xor_sync(0xFFFFFFFFu, mn, o));
            mx = fmaxf(mx, __shfl_xor_sync(0xFFFFFFFFu, mx, o));
        }
        __shared__ float rmn[THREADS / 32], rmx[THREADS / 32];
        int wid = threadIdx.x >> 5;
        int lid = threadIdx.x & 31;
        if (lid == 0) { rmn[wid] = mn; rmx[wid] = mx; }
        // zero smem histogram replicas while waiting
        for (int j = threadIdx.x; j < NCOPIES * NBINS; j += THREADS) sh[j] = 0u;
        __syncthreads();
        if (threadIdx.x == 0) {
            float fmn = rmn[0], fmx = rmx[0];
            #pragma unroll
            for (int w = 1; w < THREADS / 32; w++) {
                fmn = fminf(fmn, rmn[w]);
                fmx = fmaxf(fmx, rmx[w]);
            }
            if (fmx == fmn) fmx = fmn + 1.0f;   // degenerate-range guard (matches reference)
            s_hmin = fmn;
            s_hmax = fmx;
        }
        __syncthreads();
    }

    const float hmin  = s_hmin;
    const float scale = (float)NBINS / (s_hmax - hmin);

    unsigned int* my = sh + ((threadIdx.x >> 5) & (NCOPIES - 1)) * NBINS;

    int n4 = n >> 2;
    const float4* __restrict__ x4 = (const float4*)x;
    const int stride = GRID * THREADS;
    int i = blockIdx.x * THREADS + threadIdx.x;

    for (; i + 3 * stride < n4; i += 4 * stride) {
        float4 v0 = x4[i];
        float4 v1 = x4[i + stride];
        float4 v2 = x4[i + 2 * stride];
        float4 v3 = x4[i + 3 * stride];
        atomicAdd(&my[bin_of(v0.x, hmin, scale)], 1u);
        atomicAdd(&my[bin_of(v0.y, hmin, scale)], 1u);
        atomicAdd(&my[bin_of(v0.z, hmin, scale)], 1u);
        atomicAdd(&my[bin_of(v0.w, hmin, scale)], 1u);
        atomicAdd(&my[bin_of(v1.x, hmin, scale)], 1u);
        atomicAdd(&my[bin_of(v1.y, hmin, scale)], 1u);
        atomicAdd(&my[bin_of(v1.z, hmin, scale)], 1u);
        atomicAdd(&my[bin_of(v1.w, hmin, scale)], 1u);
        atomicAdd(&my[bin_of(v2.x, hmin, scale)], 1u);
        atomicAdd(&my[bin_of(v2.y, hmin, scale)], 1u);
        atomicAdd(&my[bin_of(v2.z, hmin, scale)], 1u);
        atomicAdd(&my[bin_of(v2.w, hmin, scale)], 1u);
        atomicAdd(&my[bin_of(v3.x, hmin, scale)], 1u);
        atomicAdd(&my[bin_of(v3.y, hmin, scale)], 1u);
        atomicAdd(&my[bin_of(v3.z, hmin, scale)], 1u);
        atomicAdd(&my[bin_of(v3.w, hmin, scale)], 1u);
    }
    for (; i < n4; i += stride) {
        float4 v = x4[i];
        atomicAdd(&my[bin_of(v.x, hmin, scale)], 1u);
        atomicAdd(&my[bin_of(v.y, hmin, scale)], 1u);
        atomicAdd(&my[bin_of(v.z, hmin, scale)], 1u);
        atomicAdd(&my[bin_of(v.w, hmin, scale)], 1u);
    }
    if (blockIdx.x == 0) {
        int base = n4 << 2;
        for (int j = base + threadIdx.x; j < n; j += THREADS) {
            atomicAdd(&my[bin_of(x[j], hmin, scale)], 1u);
        }
    }
    __syncthreads();

    // reduce replicas, one global atomic per (block, bin)
    for (int b = threadIdx.x; b < NBINS; b += THREADS) {
        unsigned int s = 0;
        #pragma unroll
        for (int c = 0; c < NCOPIES; c++) s += sh[c * NBINS + b];
        if (s) atomicAdd(&g_hist[b], s);
    }

    // ---- fused finalize: last block converts g_hist -> out, restores zeros ----
    __threadfence();
    __syncthreads();
    __shared__ unsigned int s_ticket;
    if (threadIdx.x == 0) s_ticket = atomicAdd(&g_done, 1u);
    __syncthreads();
    if (s_ticket == GRID - 1) {
        __threadfence();
        for (int b = threadIdx.x; b < NBINS; b += THREADS) {
            out[b] = (float)g_hist[b];
            g_hist[b] = 0u;            // restore zero state for next replay
        }
        if (threadIdx.x == 0) g_done = 0u;
    }
}

extern "C" void kernel_launch(void* const* d_in, const int* in_sizes, int n_in,
                              void* d_out, int out_size) {
    const float* x = (const float*)d_in[0];
    int n = in_sizes[0];
    float* out = (float*)d_out;

    minmax_kernel<<<GRID, THREADS>>>(x, n);
    hist_kernel<<<GRID, THREADS>>>(x, n, out);
}